// round 7
// baseline (speedup 1.0000x reference)
#include <cuda_runtime.h>
#include <cstdint>

#define D 64
#define H 128
#define NMAX 50048

__device__ __align__(16) float g_P[(size_t)NMAX * H];
__device__ __align__(16) float g_Q[(size_t)NMAX * H];
__device__ int g_ctr_pre;
__device__ int g_ctr_edge;

typedef unsigned long long ull;

__device__ __forceinline__ float sigt(float x) {
    float t;
    asm("tanh.approx.f32 %0, %1;" : "=f"(t) : "f"(x * 0.5f));
    return fmaf(t, 0.5f, 0.5f);
}
__device__ __forceinline__ uint32_t cvt_bf16x2(float hi, float lo) {
    uint32_t r; asm("cvt.rn.bf16x2.f32 %0, %1, %2;" : "=r"(r) : "f"(hi), "f"(lo)); return r;
}
__device__ __forceinline__ float bf_lo(uint32_t u) { return __uint_as_float(u << 16); }
__device__ __forceinline__ float bf_hi(uint32_t u) { return __uint_as_float(u & 0xffff0000u); }

__device__ __forceinline__ void mma_bf16(float* c, uint4 a, uint2 b) {
    asm volatile(
        "mma.sync.aligned.m16n8k16.row.col.f32.bf16.bf16.f32 "
        "{%0,%1,%2,%3}, {%4,%5,%6,%7}, {%8,%9}, {%0,%1,%2,%3};"
        : "+f"(c[0]), "+f"(c[1]), "+f"(c[2]), "+f"(c[3])
        : "r"(a.x), "r"(a.y), "r"(a.z), "r"(a.w), "r"(b.x), "r"(b.y));
}

// Build hi/lo bf16 A-fragments (m16n8k16 row-major layout, empirically validated
// in R5) from a 32-row fp32 scratch slab with ncols = nkt*16.
__device__ __forceinline__ void build_frags(const float* scr, uint4* hiA, uint4* loA,
                                            int mt_base, int nkt, int t, int nth)
{
    const int ncols = nkt * 16;
    for (int fid = t; fid < 64 * nkt; fid += nth) {
        int fl = fid & 31;
        int kt = (fid >> 5) % nkt;
        int mtl = fid / (32 * nkt);
        int fg = fl >> 2, ft = fl & 3;
        int lr0 = mtl * 16 + fg, lr1 = lr0 + 8;
        int k0 = kt * 16 + ft * 2;
        float w00 = scr[lr0 * ncols + k0],     w01 = scr[lr0 * ncols + k0 + 1];
        float w10 = scr[lr1 * ncols + k0],     w11 = scr[lr1 * ncols + k0 + 1];
        float w02 = scr[lr0 * ncols + k0 + 8], w03 = scr[lr0 * ncols + k0 + 9];
        float w12 = scr[lr1 * ncols + k0 + 8], w13 = scr[lr1 * ncols + k0 + 9];
        uint4 hi, lo;
        hi.x = cvt_bf16x2(w01, w00); lo.x = cvt_bf16x2(w01 - bf_hi(hi.x), w00 - bf_lo(hi.x));
        hi.y = cvt_bf16x2(w11, w10); lo.y = cvt_bf16x2(w11 - bf_hi(hi.y), w10 - bf_lo(hi.y));
        hi.z = cvt_bf16x2(w03, w02); lo.z = cvt_bf16x2(w03 - bf_hi(hi.z), w02 - bf_lo(hi.z));
        hi.w = cvt_bf16x2(w13, w12); lo.w = cvt_bf16x2(w13 - bf_hi(hi.w), w12 - bf_lo(hi.w));
        int idx = ((mt_base + mtl) * nkt + kt) * 32 + fl;
        hiA[idx] = hi;
        loA[idx] = lo;
    }
}

// Stage 4 consecutive-k values (k%4==0) for fragment-column n of group nt into
// hi/lo B buffers. Writer XOR = e>>2 (= 2*nt + n>>2); reader applies the same.
__device__ __forceinline__ void stage4(uint32_t* hiB, uint32_t* loB,
                                       int nt, int n, int xe, int k,
                                       float z0, float z1, float z2, float z3)
{
    uint32_t h01 = cvt_bf16x2(z1, z0);
    uint32_t l01 = cvt_bf16x2(z1 - bf_hi(h01), z0 - bf_lo(h01));
    uint32_t h23 = cvt_bf16x2(z3, z2);
    uint32_t l23 = cvt_bf16x2(z3 - bf_hi(h23), z2 - bf_lo(h23));
    int kt = k >> 4, kq = (k & 7) >> 1, reg = (k >> 3) & 1;
    int l0 = (n * 4 + kq) ^ xe, l1 = (n * 4 + kq + 1) ^ xe;
    int base = (nt * 8 + kt) * 64;
    hiB[base + l0 * 2 + reg] = h01;
    hiB[base + l1 * 2 + reg] = h23;
    loB[base + l0 * 2 + reg] = l01;
    loB[base + l1 * 2 + reg] = l23;
}

__global__ void init_ctrs() { g_ctr_pre = 0; g_ctr_edge = 0; }

// ---------------------------------------------------------------------------
// Precompute: P[n] = b1 + [Wa | Wc+Wd] @ [h1;h2],  Q[n] = Wb @ h1
// 256 threads, 8 independent warps, 32 nodes per warp-tile, bf16x3 HMMA.
// ---------------------------------------------------------------------------
#define P_A1HI 0
#define P_A1LO 32768
#define P_A2HI 65536
#define P_A2LO 81920
#define P_B    98304            // 8 warps x 16KB (hi 8KB + lo 8KB)
#define P_B1S  229376
#define PRE_SMEM_BYTES 229888

__global__ void __launch_bounds__(256) precompute_kernel(
    const float* __restrict__ h1, const float* __restrict__ h2,
    const float* __restrict__ W1, const float* __restrict__ b1, int n)
{
    extern __shared__ char smc[];
    uint4* A1hi = (uint4*)(smc + P_A1HI);
    uint4* A1lo = (uint4*)(smc + P_A1LO);
    uint4* A2hi = (uint4*)(smc + P_A2HI);
    uint4* A2lo = (uint4*)(smc + P_A2LO);
    float* b1s = (float*)(smc + P_B1S);

    const int t = threadIdx.x, lane = t & 31, w = t >> 5;
    const int gid = lane >> 2, tig = lane & 3;

    // Build A1 = [Wa | Wc+Wd] (128x128) and A2 = Wb (128x64) fragments.
    {
        float* scr = (float*)(smc + P_B);   // 16KB scratch (reuses B region)
        for (int chunk = 0; chunk < 4; ++chunk) {
            const int R0 = chunk * 32;
            __syncthreads();
            for (int idx = t; idx < 4096; idx += 256) {
                int r = idx >> 7, k = idx & 127;
                float v;
                if (k < 64) v = W1[(R0 + r) * 256 + k];
                else        v = W1[(R0 + r) * 256 + 64 + k] + W1[(R0 + r) * 256 + 128 + k];
                scr[r * 128 + k] = v;
            }
            __syncthreads();
            build_frags(scr, A1hi, A1lo, chunk * 2, 8, t, 256);
        }
        for (int chunk = 0; chunk < 4; ++chunk) {
            const int R0 = chunk * 32;
            __syncthreads();
            for (int idx = t; idx < 2048; idx += 256) {
                int r = idx >> 6, k = idx & 63;
                scr[r * 64 + k] = W1[(R0 + r) * 256 + 64 + k];
            }
            __syncthreads();
            build_frags(scr, A2hi, A2lo, chunk * 2, 4, t, 256);
        }
    }
    if (t < 128) b1s[t] = b1[t];
    __syncthreads();

    float b1r0[8], b1r1[8];
    #pragma unroll
    for (int mt = 0; mt < 8; ++mt) {
        b1r0[mt] = b1s[mt * 16 + gid];
        b1r1[mt] = b1s[mt * 16 + gid + 8];
    }

    uint32_t* hiB = (uint32_t*)(smc + P_B + w * 16384);
    uint32_t* loB = hiB + 2048;
    const int e = lane, nt_e = e >> 3, n_e = e & 7, xe = e >> 2;
    const int lq = lane >> 4;
    const int ntiles = (n + 31) >> 5;

    for (;;) {
        int tile;
        if (lane == 0) tile = atomicAdd(&g_ctr_pre, 1);
        tile = __shfl_sync(0xffffffffu, tile, 0);
        if (tile >= ntiles) break;
        const int nb = tile * 32;
        const int node = nb + e;
        __syncwarp();

        // stage B = [h1(64); h2(64)] hi/lo for this lane's node
        if (node < n) {
            const float4* H1 = (const float4*)(h1 + (size_t)node * D);
            const float4* H2 = (const float4*)(h2 + (size_t)node * D);
            #pragma unroll 8
            for (int u = 0; u < 16; ++u) {
                float4 v = H1[u];
                stage4(hiB, loB, nt_e, n_e, xe, u * 4, v.x, v.y, v.z, v.w);
            }
            #pragma unroll 8
            for (int u = 0; u < 16; ++u) {
                float4 v = H2[u];
                stage4(hiB, loB, nt_e, n_e, xe, 64 + u * 4, v.x, v.y, v.z, v.w);
            }
        } else {
            #pragma unroll 8
            for (int u = 0; u < 32; ++u)
                stage4(hiB, loB, nt_e, n_e, xe, u * 4, 0.f, 0.f, 0.f, 0.f);
        }
        __syncwarp();

        float acc[8][4][4];

        // ---- P pass: A1, K=128
        #pragma unroll
        for (int mt = 0; mt < 8; ++mt)
            #pragma unroll
            for (int nt = 0; nt < 4; ++nt)
                #pragma unroll
                for (int r = 0; r < 4; ++r) acc[mt][nt][r] = 0.f;

        #pragma unroll 1
        for (int kt = 0; kt < 8; ++kt) {
            uint2 bh[4], bo[4];
            #pragma unroll
            for (int nt = 0; nt < 4; ++nt) {
                int lp = lane ^ (2 * nt + lq);
                bh[nt] = ((const uint2*)hiB)[(nt * 8 + kt) * 32 + lp];
                bo[nt] = ((const uint2*)loB)[(nt * 8 + kt) * 32 + lp];
            }
            #pragma unroll
            for (int mt = 0; mt < 8; ++mt) {
                uint4 ah = A1hi[(mt * 8 + kt) * 32 + lane];
                uint4 al = A1lo[(mt * 8 + kt) * 32 + lane];
                #pragma unroll
                for (int nt = 0; nt < 4; ++nt) {
                    mma_bf16(acc[mt][nt], ah, bh[nt]);
                    mma_bf16(acc[mt][nt], ah, bo[nt]);
                    mma_bf16(acc[mt][nt], al, bh[nt]);
                }
            }
        }
        #pragma unroll
        for (int nt = 0; nt < 4; ++nt) {
            int n0 = nb + nt * 8 + tig * 2, n1 = n0 + 1;
            #pragma unroll
            for (int mt = 0; mt < 8; ++mt) {
                int r0 = mt * 16 + gid, r1 = r0 + 8;
                if (n0 < n) {
                    g_P[(size_t)n0 * H + r0] = acc[mt][nt][0] + b1r0[mt];
                    g_P[(size_t)n0 * H + r1] = acc[mt][nt][2] + b1r1[mt];
                }
                if (n1 < n) {
                    g_P[(size_t)n1 * H + r0] = acc[mt][nt][1] + b1r0[mt];
                    g_P[(size_t)n1 * H + r1] = acc[mt][nt][3] + b1r1[mt];
                }
            }
        }

        // ---- Q pass: A2, K=64 (B slabs kt 0..3 hold h1)
        #pragma unroll
        for (int mt = 0; mt < 8; ++mt)
            #pragma unroll
            for (int nt = 0; nt < 4; ++nt)
                #pragma unroll
                for (int r = 0; r < 4; ++r) acc[mt][nt][r] = 0.f;

        #pragma unroll 1
        for (int kt = 0; kt < 4; ++kt) {
            uint2 bh[4], bo[4];
            #pragma unroll
            for (int nt = 0; nt < 4; ++nt) {
                int lp = lane ^ (2 * nt + lq);
                bh[nt] = ((const uint2*)hiB)[(nt * 8 + kt) * 32 + lp];
                bo[nt] = ((const uint2*)loB)[(nt * 8 + kt) * 32 + lp];
            }
            #pragma unroll
            for (int mt = 0; mt < 8; ++mt) {
                uint4 ah = A2hi[(mt * 4 + kt) * 32 + lane];
                uint4 al = A2lo[(mt * 4 + kt) * 32 + lane];
                #pragma unroll
                for (int nt = 0; nt < 4; ++nt) {
                    mma_bf16(acc[mt][nt], ah, bh[nt]);
                    mma_bf16(acc[mt][nt], ah, bo[nt]);
                    mma_bf16(acc[mt][nt], al, bh[nt]);
                }
            }
        }
        #pragma unroll
        for (int nt = 0; nt < 4; ++nt) {
            int n0 = nb + nt * 8 + tig * 2, n1 = n0 + 1;
            #pragma unroll
            for (int mt = 0; mt < 8; ++mt) {
                int r0 = mt * 16 + gid, r1 = r0 + 8;
                if (n0 < n) {
                    g_Q[(size_t)n0 * H + r0] = acc[mt][nt][0];
                    g_Q[(size_t)n0 * H + r1] = acc[mt][nt][2];
                }
                if (n1 < n) {
                    g_Q[(size_t)n1 * H + r0] = acc[mt][nt][1];
                    g_Q[(size_t)n1 * H + r1] = acc[mt][nt][3];
                }
            }
        }
    }
}

// ---------------------------------------------------------------------------
// Edge kernel: warp-independent, 32 edges per warp-tile, bf16x3 HMMA.
// ---------------------------------------------------------------------------
#define E_AHI 0
#define E_ALO 32768
#define E_B   65536             // 8 warps x 16KB
#define E_B2S 196608
#define E_W3S 197120
#define EDGE_SMEM_BYTES 197632

__global__ void __launch_bounds__(256) edge_kernel(
    const int* __restrict__ src, const int* __restrict__ dst,
    const float* __restrict__ W2, const float* __restrict__ b2,
    const float* __restrict__ W3, const float* __restrict__ b3,
    float* __restrict__ out, int E, int n)
{
    extern __shared__ char smc[];
    uint4* Ahi = (uint4*)(smc + E_AHI);
    uint4* Alo = (uint4*)(smc + E_ALO);
    float* b2s = (float*)(smc + E_B2S);
    float* w3s = (float*)(smc + E_W3S);

    const int t = threadIdx.x, lane = t & 31, w = t >> 5;
    const int gid = lane >> 2, tig = lane & 3;

    // Build W2 fragments (hi/lo) once.
    {
        float* scr = (float*)(smc + E_B);
        for (int chunk = 0; chunk < 4; ++chunk) {
            __syncthreads();
            for (int i = t; i < 1024; i += 256)
                ((float4*)scr)[i] = ((const float4*)W2)[chunk * 1024 + i];
            __syncthreads();
            build_frags(scr, Ahi, Alo, chunk * 2, 8, t, 256);
        }
    }
    if (t < 128) { b2s[t] = b2[t]; w3s[t] = W3[t]; }
    __syncthreads();

    float b2r0[8], b2r1[8], w3r0[8], w3r1[8];
    #pragma unroll
    for (int mt = 0; mt < 8; ++mt) {
        b2r0[mt] = b2s[mt * 16 + gid];
        b2r1[mt] = b2s[mt * 16 + gid + 8];
        w3r0[mt] = w3s[mt * 16 + gid];
        w3r1[mt] = w3s[mt * 16 + gid + 8];
    }
    const float b3v = b3[0];

    uint32_t* hiB = (uint32_t*)(smc + E_B + w * 16384);
    uint32_t* loB = hiB + 2048;
    const int e = lane, nt_e = e >> 3, n_e = e & 7, xe = e >> 2;
    const int lq = lane >> 4;
    const int ntiles = (E + 31) >> 5;

    for (;;) {
        int tile;
        if (lane == 0) tile = atomicAdd(&g_ctr_edge, 1);
        tile = __shfl_sync(0xffffffffu, tile, 0);
        if (tile >= ntiles) break;
        const int e0 = tile * 32;
        const int ge = e0 + e;
        __syncwarp();

        // stage z1 = sigmoid(P[src] + Q[dst]) hi/lo for this lane's edge
        if (ge < E) {
            int s = min(max(src[ge], 0), n - 1);
            int d = min(max(dst[ge], 0), n - 1);
            const float4* Pp = (const float4*)(g_P + (size_t)s * H);
            const float4* Qp = (const float4*)(g_Q + (size_t)d * H);
            #pragma unroll 8
            for (int u = 0; u < 32; ++u) {
                float4 p = Pp[u], q = Qp[u];
                stage4(hiB, loB, nt_e, n_e, xe, u * 4,
                       sigt(p.x + q.x), sigt(p.y + q.y),
                       sigt(p.z + q.z), sigt(p.w + q.w));
            }
        } else {
            #pragma unroll 8
            for (int u = 0; u < 32; ++u)
                stage4(hiB, loB, nt_e, n_e, xe, u * 4, 0.f, 0.f, 0.f, 0.f);
        }
        __syncwarp();

        float acc[8][4][4];
        #pragma unroll
        for (int mt = 0; mt < 8; ++mt)
            #pragma unroll
            for (int nt = 0; nt < 4; ++nt)
                #pragma unroll
                for (int r = 0; r < 4; ++r) acc[mt][nt][r] = 0.f;

        #pragma unroll 1
        for (int kt = 0; kt < 8; ++kt) {
            uint2 bh[4], bo[4];
            #pragma unroll
            for (int nt = 0; nt < 4; ++nt) {
                int lp = lane ^ (2 * nt + lq);
                bh[nt] = ((const uint2*)hiB)[(nt * 8 + kt) * 32 + lp];
                bo[nt] = ((const uint2*)loB)[(nt * 8 + kt) * 32 + lp];
            }
            #pragma unroll
            for (int mt = 0; mt < 8; ++mt) {
                uint4 ah = Ahi[(mt * 8 + kt) * 32 + lane];
                uint4 al = Alo[(mt * 8 + kt) * 32 + lane];
                #pragma unroll
                for (int nt = 0; nt < 4; ++nt) {
                    mma_bf16(acc[mt][nt], ah, bh[nt]);
                    mma_bf16(acc[mt][nt], ah, bo[nt]);
                    mma_bf16(acc[mt][nt], al, bh[nt]);
                }
            }
        }

        // epilogue: sigmoid + W3 dot, reduce over gid (lane bits 2..4)
        #pragma unroll
        for (int nt = 0; nt < 4; ++nt) {
            float s0 = 0.f, s1 = 0.f;
            #pragma unroll
            for (int mt = 0; mt < 8; ++mt) {
                s0 += sigt(acc[mt][nt][0] + b2r0[mt]) * w3r0[mt]
                    + sigt(acc[mt][nt][2] + b2r1[mt]) * w3r1[mt];
                s1 += sigt(acc[mt][nt][1] + b2r0[mt]) * w3r0[mt]
                    + sigt(acc[mt][nt][3] + b2r1[mt]) * w3r1[mt];
            }
            #pragma unroll
            for (int off = 4; off <= 16; off <<= 1) {
                s0 += __shfl_xor_sync(0xffffffffu, s0, off);
                s1 += __shfl_xor_sync(0xffffffffu, s1, off);
            }
            if (gid == 0) {
                int go = e0 + nt * 8 + tig * 2;
                if (go + 1 < E)
                    *(float2*)(out + go) = make_float2(s0 + b3v, s1 + b3v);
                else if (go < E)
                    out[go] = s0 + b3v;
            }
        }
    }
}

extern "C" void kernel_launch(void* const* d_in, const int* in_sizes, int n_in,
                              void* d_out, int out_size)
{
    const float* h1 = (const float*)d_in[0];
    const float* h2 = (const float*)d_in[1];
    const int* src = (const int*)d_in[2];
    const int* dst = (const int*)d_in[3];
    const float* W1 = (const float*)d_in[4];
    const float* b1 = (const float*)d_in[5];
    const float* W2 = (const float*)d_in[6];
    const float* b2 = (const float*)d_in[7];
    const float* W3 = (const float*)d_in[8];
    const float* b3 = (const float*)d_in[9];
    float* out = (float*)d_out;

    const int n = in_sizes[0] / D;
    const int E = in_sizes[2];

    cudaFuncSetAttribute(precompute_kernel,
                         cudaFuncAttributeMaxDynamicSharedMemorySize, PRE_SMEM_BYTES);
    cudaFuncSetAttribute(edge_kernel,
                         cudaFuncAttributeMaxDynamicSharedMemorySize, EDGE_SMEM_BYTES);

    init_ctrs<<<1, 1>>>();
    precompute_kernel<<<148, 256, PRE_SMEM_BYTES>>>(h1, h2, W1, b1, n);
    edge_kernel<<<148, 256, EDGE_SMEM_BYTES>>>(src, dst, W2, b2, W3, b3, out, E, n);
}

// round 8
// speedup vs baseline: 1.6813x; 1.6813x over previous
#include <cuda_runtime.h>
#include <cuda_fp16.h>
#include <cstdint>

#define D 64
#define H 128
#define NMAX 50048

// Node-factored layer-1 preactivations, fp16 (halves gather traffic)
__device__ __align__(16) __half g_P[(size_t)NMAX * H];
__device__ __align__(16) __half g_Q[(size_t)NMAX * H];
__device__ int g_ctr_pre;    // reset by edge_kernel (for next replay)
__device__ int g_ctr_edge;   // reset by precompute_kernel (runs first)

__device__ __forceinline__ float sigt(float x) {
    float t;
    asm("tanh.approx.f32 %0, %1;" : "=f"(t) : "f"(x * 0.5f));
    return fmaf(t, 0.5f, 0.5f);
}
__device__ __forceinline__ uint32_t f16x2(float lo, float hi) {
    __half2 h = __floats2half2_rn(lo, hi);   // lo -> low half, hi -> high half
    return *(uint32_t*)&h;
}
__device__ __forceinline__ float2 h2f2(uint32_t u) {
    return __half22float2(*(__half2*)&u);
}

// fp16 m16n8k16 row.col MMA, fp32 accum
__device__ __forceinline__ void mma_f16(float* c, uint4 a, uint2 b) {
    asm volatile(
        "mma.sync.aligned.m16n8k16.row.col.f32.f16.f16.f32 "
        "{%0,%1,%2,%3}, {%4,%5,%6,%7}, {%8,%9}, {%0,%1,%2,%3};"
        : "+f"(c[0]), "+f"(c[1]), "+f"(c[2]), "+f"(c[3])
        : "r"(a.x), "r"(a.y), "r"(a.z), "r"(a.w), "r"(b.x), "r"(b.y));
}

// Build fp16 A-fragments (m16n8k16 row-major layout, validated R5-R7) from a
// 32-row fp32 scratch slab, ncols = nkt*16.
__device__ __forceinline__ void build_frags_h(const float* scr, uint4* A,
                                              int mt_base, int nkt, int t, int nth)
{
    const int ncols = nkt * 16;
    for (int fid = t; fid < 64 * nkt; fid += nth) {
        int fl = fid & 31;
        int kt = (fid >> 5) % nkt;
        int mtl = fid / (32 * nkt);
        int fg = fl >> 2, ft = fl & 3;
        int lr0 = mtl * 16 + fg, lr1 = lr0 + 8;
        int k0 = kt * 16 + ft * 2;
        uint4 hi;
        hi.x = f16x2(scr[lr0 * ncols + k0],     scr[lr0 * ncols + k0 + 1]);
        hi.y = f16x2(scr[lr1 * ncols + k0],     scr[lr1 * ncols + k0 + 1]);
        hi.z = f16x2(scr[lr0 * ncols + k0 + 8], scr[lr0 * ncols + k0 + 9]);
        hi.w = f16x2(scr[lr1 * ncols + k0 + 8], scr[lr1 * ncols + k0 + 9]);
        A[((mt_base + mtl) * nkt + kt) * 32 + fl] = hi;
    }
}

// Stage 4 consecutive-k values (k%4==0) for fragment-column nn of group nt.
// Writer XOR = e>>2; reader uses lane ^ (2*nt + lane>>4). Validated R6/7.
__device__ __forceinline__ void stage4h(uint32_t* B, int nt, int nn, int xe, int k,
                                        float z0, float z1, float z2, float z3)
{
    uint32_t h01 = f16x2(z0, z1);
    uint32_t h23 = f16x2(z2, z3);
    int kt = k >> 4, kq = (k & 7) >> 1, reg = (k >> 3) & 1;
    int l0 = (nn * 4 + kq) ^ xe, l1 = (nn * 4 + kq + 1) ^ xe;
    int base = (nt * 8 + kt) * 64;
    B[base + l0 * 2 + reg] = h01;
    B[base + l1 * 2 + reg] = h23;
}

// ---------------------------------------------------------------------------
// Precompute: P[n] = b1 + [Wa | Wc+Wd] @ [h1;h2],  Q[n] = Wb @ h1  (fp16 out)
// 256 threads, 8 independent warps, 32 nodes per warp-tile, fp16 HMMA.
// ---------------------------------------------------------------------------
#define P_A1 0                  // 32 KB
#define P_A2 32768              // 16 KB
#define P_B  49152              // 8 warps x 8 KB
#define P_B1S 114688
#define PRE_SMEM_BYTES 115712

__global__ void __launch_bounds__(256) precompute_kernel(
    const float* __restrict__ h1, const float* __restrict__ h2,
    const float* __restrict__ W1, const float* __restrict__ b1, int n)
{
    extern __shared__ char smc[];
    uint4* A1 = (uint4*)(smc + P_A1);
    uint4* A2 = (uint4*)(smc + P_A2);
    float* b1s = (float*)(smc + P_B1S);

    const int t = threadIdx.x, lane = t & 31, w = t >> 5;
    const int gid = lane >> 2, tig = lane & 3;

    if (blockIdx.x == 0 && t == 0) g_ctr_edge = 0;   // reset for edge_kernel

    // Build A1 = [Wa | Wc+Wd] (128x128) and A2 = Wb (128x64) fp16 fragments.
    {
        float* scr = (float*)(smc + P_B);   // 16KB scratch (reuses B region)
        for (int chunk = 0; chunk < 4; ++chunk) {
            const int R0 = chunk * 32;
            __syncthreads();
            for (int idx = t; idx < 4096; idx += 256) {
                int r = idx >> 7, k = idx & 127;
                float v;
                if (k < 64) v = W1[(R0 + r) * 256 + k];
                else        v = W1[(R0 + r) * 256 + 64 + k] + W1[(R0 + r) * 256 + 128 + k];
                scr[r * 128 + k] = v;
            }
            __syncthreads();
            build_frags_h(scr, A1, chunk * 2, 8, t, 256);
        }
        for (int chunk = 0; chunk < 4; ++chunk) {
            const int R0 = chunk * 32;
            __syncthreads();
            for (int idx = t; idx < 2048; idx += 256) {
                int r = idx >> 6, k = idx & 63;
                scr[r * 64 + k] = W1[(R0 + r) * 256 + 64 + k];
            }
            __syncthreads();
            build_frags_h(scr, A2, chunk * 2, 4, t, 256);
        }
    }
    if (t < 128) b1s[t] = b1[t];
    __syncthreads();

    float b1r0[8], b1r1[8];
    #pragma unroll
    for (int mt = 0; mt < 8; ++mt) {
        b1r0[mt] = b1s[mt * 16 + gid];
        b1r1[mt] = b1s[mt * 16 + gid + 8];
    }

    uint32_t* Bw = (uint32_t*)(smc + P_B + w * 8192);
    const int e = lane, nt_e = e >> 3, n_e = e & 7, xe = e >> 2;
    const int lq = lane >> 4;
    const int ntiles = (n + 31) >> 5;

    for (;;) {
        int tile;
        if (lane == 0) tile = atomicAdd(&g_ctr_pre, 1);
        tile = __shfl_sync(0xffffffffu, tile, 0);
        if (tile >= ntiles) break;
        const int nb = tile * 32;
        const int node = nb + e;
        __syncwarp();

        if (node < n) {
            const float4* H1 = (const float4*)(h1 + (size_t)node * D);
            const float4* H2 = (const float4*)(h2 + (size_t)node * D);
            #pragma unroll 8
            for (int u = 0; u < 16; ++u) {
                float4 v = H1[u];
                stage4h(Bw, nt_e, n_e, xe, u * 4, v.x, v.y, v.z, v.w);
            }
            #pragma unroll 8
            for (int u = 0; u < 16; ++u) {
                float4 v = H2[u];
                stage4h(Bw, nt_e, n_e, xe, 64 + u * 4, v.x, v.y, v.z, v.w);
            }
        } else {
            #pragma unroll 8
            for (int u = 0; u < 32; ++u)
                stage4h(Bw, nt_e, n_e, xe, u * 4, 0.f, 0.f, 0.f, 0.f);
        }
        __syncwarp();

        float acc[8][4][4];

        // ---- P pass: A1, K=128
        #pragma unroll
        for (int mt = 0; mt < 8; ++mt)
            #pragma unroll
            for (int nt = 0; nt < 4; ++nt)
                #pragma unroll
                for (int r = 0; r < 4; ++r) acc[mt][nt][r] = 0.f;

        #pragma unroll 1
        for (int kt = 0; kt < 8; ++kt) {
            uint2 bh[4];
            #pragma unroll
            for (int nt = 0; nt < 4; ++nt)
                bh[nt] = ((const uint2*)Bw)[(nt * 8 + kt) * 32 + (lane ^ (2 * nt + lq))];
            #pragma unroll
            for (int mt = 0; mt < 8; ++mt) {
                uint4 ah = A1[(mt * 8 + kt) * 32 + lane];
                #pragma unroll
                for (int nt = 0; nt < 4; ++nt) mma_f16(acc[mt][nt], ah, bh[nt]);
            }
        }
        #pragma unroll
        for (int nt = 0; nt < 4; ++nt) {
            int n0 = nb + nt * 8 + tig * 2, n1 = n0 + 1;
            #pragma unroll
            for (int mt = 0; mt < 8; ++mt) {
                int r0 = mt * 16 + gid, r1 = r0 + 8;
                if (n0 < n) {
                    g_P[(size_t)n0 * H + r0] = __float2half_rn(acc[mt][nt][0] + b1r0[mt]);
                    g_P[(size_t)n0 * H + r1] = __float2half_rn(acc[mt][nt][2] + b1r1[mt]);
                }
                if (n1 < n) {
                    g_P[(size_t)n1 * H + r0] = __float2half_rn(acc[mt][nt][1] + b1r0[mt]);
                    g_P[(size_t)n1 * H + r1] = __float2half_rn(acc[mt][nt][3] + b1r1[mt]);
                }
            }
        }

        // ---- Q pass: A2, K=64 (B slabs kt 0..3 hold h1)
        #pragma unroll
        for (int mt = 0; mt < 8; ++mt)
            #pragma unroll
            for (int nt = 0; nt < 4; ++nt)
                #pragma unroll
                for (int r = 0; r < 4; ++r) acc[mt][nt][r] = 0.f;

        #pragma unroll 1
        for (int kt = 0; kt < 4; ++kt) {
            uint2 bh[4];
            #pragma unroll
            for (int nt = 0; nt < 4; ++nt)
                bh[nt] = ((const uint2*)Bw)[(nt * 8 + kt) * 32 + (lane ^ (2 * nt + lq))];
            #pragma unroll
            for (int mt = 0; mt < 8; ++mt) {
                uint4 ah = A2[(mt * 4 + kt) * 32 + lane];
                #pragma unroll
                for (int nt = 0; nt < 4; ++nt) mma_f16(acc[mt][nt], ah, bh[nt]);
            }
        }
        #pragma unroll
        for (int nt = 0; nt < 4; ++nt) {
            int n0 = nb + nt * 8 + tig * 2, n1 = n0 + 1;
            #pragma unroll
            for (int mt = 0; mt < 8; ++mt) {
                int r0 = mt * 16 + gid, r1 = r0 + 8;
                if (n0 < n) {
                    g_Q[(size_t)n0 * H + r0] = __float2half_rn(acc[mt][nt][0]);
                    g_Q[(size_t)n0 * H + r1] = __float2half_rn(acc[mt][nt][2]);
                }
                if (n1 < n) {
                    g_Q[(size_t)n1 * H + r0] = __float2half_rn(acc[mt][nt][1]);
                    g_Q[(size_t)n1 * H + r1] = __float2half_rn(acc[mt][nt][3]);
                }
            }
        }
    }
}

// ---------------------------------------------------------------------------
// Edge kernel: warp-independent, 32 edges per warp-tile, single-pass fp16 HMMA.
// ---------------------------------------------------------------------------
#define E_A   0                 // 32 KB
#define E_B   32768             // 8 warps x 8 KB
#define E_B2S 98304
#define E_W3S 98816
#define EDGE_SMEM_BYTES 99840

__global__ void __launch_bounds__(256) edge_kernel(
    const int* __restrict__ src, const int* __restrict__ dst,
    const float* __restrict__ W2, const float* __restrict__ b2,
    const float* __restrict__ W3, const float* __restrict__ b3,
    float* __restrict__ out, int E, int n)
{
    extern __shared__ char smc[];
    uint4* Ahi = (uint4*)(smc + E_A);
    float* b2s = (float*)(smc + E_B2S);
    float* w3s = (float*)(smc + E_W3S);

    const int t = threadIdx.x, lane = t & 31, w = t >> 5;
    const int gid = lane >> 2, tig = lane & 3;

    if (blockIdx.x == 0 && t == 0) g_ctr_pre = 0;    // reset for next replay

    // Build W2 fp16 fragments once.
    {
        float* scr = (float*)(smc + E_B);
        for (int chunk = 0; chunk < 4; ++chunk) {
            __syncthreads();
            for (int i = t; i < 1024; i += 256)
                ((float4*)scr)[i] = ((const float4*)W2)[chunk * 1024 + i];
            __syncthreads();
            build_frags_h(scr, Ahi, chunk * 2, 8, t, 256);
        }
    }
    if (t < 128) { b2s[t] = b2[t]; w3s[t] = W3[t]; }
    __syncthreads();

    float b2r0[8], b2r1[8], w3r0[8], w3r1[8];
    #pragma unroll
    for (int mt = 0; mt < 8; ++mt) {
        b2r0[mt] = b2s[mt * 16 + gid];
        b2r1[mt] = b2s[mt * 16 + gid + 8];
        w3r0[mt] = w3s[mt * 16 + gid];
        w3r1[mt] = w3s[mt * 16 + gid + 8];
    }
    const float b3v = b3[0];

    uint32_t* Bw = (uint32_t*)(smc + E_B + w * 8192);
    const int e = lane, nt_e = e >> 3, n_e = e & 7, xe = e >> 2;
    const int lq = lane >> 4;
    const int ntiles = (E + 31) >> 5;

    for (;;) {
        int tile;
        if (lane == 0) tile = atomicAdd(&g_ctr_edge, 1);
        tile = __shfl_sync(0xffffffffu, tile, 0);
        if (tile >= ntiles) break;
        const int e0 = tile * 32;
        const int ge = e0 + e;
        __syncwarp();

        // stage z1 = sigmoid(P[src] + Q[dst]) as fp16 fragments
        if (ge < E) {
            int s = min(max(src[ge], 0), n - 1);
            int d = min(max(dst[ge], 0), n - 1);
            const uint4* Pp = (const uint4*)(g_P + (size_t)s * H);
            const uint4* Qp = (const uint4*)(g_Q + (size_t)d * H);
            #pragma unroll 4
            for (int u = 0; u < 16; ++u) {
                uint4 pv = Pp[u], qv = Qp[u];
                float2 p0 = h2f2(pv.x), q0 = h2f2(qv.x);
                float2 p1 = h2f2(pv.y), q1 = h2f2(qv.y);
                float2 p2 = h2f2(pv.z), q2 = h2f2(qv.z);
                float2 p3 = h2f2(pv.w), q3 = h2f2(qv.w);
                stage4h(Bw, nt_e, n_e, xe, u * 8,
                        sigt(p0.x + q0.x), sigt(p0.y + q0.y),
                        sigt(p1.x + q1.x), sigt(p1.y + q1.y));
                stage4h(Bw, nt_e, n_e, xe, u * 8 + 4,
                        sigt(p2.x + q2.x), sigt(p2.y + q2.y),
                        sigt(p3.x + q3.x), sigt(p3.y + q3.y));
            }
        } else {
            #pragma unroll 8
            for (int u = 0; u < 32; ++u)
                stage4h(Bw, nt_e, n_e, xe, u * 4, 0.f, 0.f, 0.f, 0.f);
        }
        __syncwarp();

        float acc[8][4][4];
        #pragma unroll
        for (int mt = 0; mt < 8; ++mt)
            #pragma unroll
            for (int nt = 0; nt < 4; ++nt)
                #pragma unroll
                for (int r = 0; r < 4; ++r) acc[mt][nt][r] = 0.f;

        #pragma unroll 1
        for (int kt = 0; kt < 8; ++kt) {
            uint2 bh[4];
            #pragma unroll
            for (int nt = 0; nt < 4; ++nt)
                bh[nt] = ((const uint2*)Bw)[(nt * 8 + kt) * 32 + (lane ^ (2 * nt + lq))];
            #pragma unroll
            for (int mt = 0; mt < 8; ++mt) {
                uint4 ah = Ahi[(mt * 8 + kt) * 32 + lane];
                #pragma unroll
                for (int nt = 0; nt < 4; ++nt) mma_f16(acc[mt][nt], ah, bh[nt]);
            }
        }

        // epilogue: sigmoid + W3 dot, reduce over gid (lane bits 2..4)
        #pragma unroll
        for (int nt = 0; nt < 4; ++nt) {
            float s0 = 0.f, s1 = 0.f;
            #pragma unroll
            for (int mt = 0; mt < 8; ++mt) {
                s0 += sigt(acc[mt][nt][0] + b2r0[mt]) * w3r0[mt]
                    + sigt(acc[mt][nt][2] + b2r1[mt]) * w3r1[mt];
                s1 += sigt(acc[mt][nt][1] + b2r0[mt]) * w3r0[mt]
                    + sigt(acc[mt][nt][3] + b2r1[mt]) * w3r1[mt];
            }
            #pragma unroll
            for (int off = 4; off <= 16; off <<= 1) {
                s0 += __shfl_xor_sync(0xffffffffu, s0, off);
                s1 += __shfl_xor_sync(0xffffffffu, s1, off);
            }
            if (gid == 0) {
                int go = e0 + nt * 8 + tig * 2;
                if (go + 1 < E)
                    *(float2*)(out + go) = make_float2(s0 + b3v, s1 + b3v);
                else if (go < E)
                    out[go] = s0 + b3v;
            }
        }
    }
}

extern "C" void kernel_launch(void* const* d_in, const int* in_sizes, int n_in,
                              void* d_out, int out_size)
{
    const float* h1 = (const float*)d_in[0];
    const float* h2 = (const float*)d_in[1];
    const int* src = (const int*)d_in[2];
    const int* dst = (const int*)d_in[3];
    const float* W1 = (const float*)d_in[4];
    const float* b1 = (const float*)d_in[5];
    const float* W2 = (const float*)d_in[6];
    const float* b2 = (const float*)d_in[7];
    const float* W3 = (const float*)d_in[8];
    const float* b3 = (const float*)d_in[9];
    float* out = (float*)d_out;

    const int n = in_sizes[0] / D;
    const int E = in_sizes[2];

    cudaFuncSetAttribute(precompute_kernel,
                         cudaFuncAttributeMaxDynamicSharedMemorySize, PRE_SMEM_BYTES);
    cudaFuncSetAttribute(edge_kernel,
                         cudaFuncAttributeMaxDynamicSharedMemorySize, EDGE_SMEM_BYTES);

    precompute_kernel<<<148, 256, PRE_SMEM_BYTES>>>(h1, h2, W1, b1, n);
    edge_kernel<<<148, 256, EDGE_SMEM_BYTES>>>(src, dst, W2, b2, W3, b3, out, E, n);
}